// round 1
// baseline (speedup 1.0000x reference)
#include <cuda_runtime.h>
#include <math_constants.h>

#define BB 64
#define SS 512
#define TT 128
#define NT 256

__device__ float g_partial[BB];

static __device__ __forceinline__ unsigned long long ffma2(unsigned long long a,
                                                           unsigned long long b,
                                                           unsigned long long c) {
    unsigned long long d;
    asm("fma.rn.f32x2 %0, %1, %2, %3;" : "=l"(d) : "l"(a), "l"(b), "l"(c));
    return d;
}
static __device__ __forceinline__ unsigned long long pack2(float x, float y) {
    unsigned long long d;
    asm("mov.b64 %0, {%1, %2};" : "=l"(d) : "f"(x), "f"(y));
    return d;
}
static __device__ __forceinline__ float2 unpack2(unsigned long long v) {
    float2 r;
    asm("mov.b64 {%0, %1}, %2;" : "=f"(r.x), "=f"(r.y) : "l"(v));
    return r;
}

__global__ __launch_bounds__(NT, 1)
void crf_kernel(const float* __restrict__ feats,
                const int* __restrict__ mask,
                const int* __restrict__ tags,
                const float* __restrict__ trans,
                const float* __restrict__ start_t,
                const float* __restrict__ stop_t)
{
    __shared__ __align__(16) float sh_q2[2 * TT];     // q duplicated: (q_i, q_i)
    __shared__ __align__(16) float sh_part[4 * TT];   // 4 i-quarter partials, pair-interleaved
    __shared__ float sh_wmax[4];
    __shared__ float sh_redf[NT / 32];
    __shared__ float sh_redl[NT / 32];

    const int b = blockIdx.x;
    const int t = threadIdx.x;
    const float* Fb = feats + (size_t)b * SS * TT;
    const int* Mk = mask + b * SS;
    const int* Tg = tags + b * SS;

    const int jp = t & 63;
    const int h = t >> 6;
    const int j0 = jp * 2;
    const int ibase = h * 32;

    // E[i][j] = exp(trans[j][i])  (reference uses transitions.T[i,j]); packed (j0, j1) per i.
    unsigned long long e2[32];
#pragma unroll
    for (int k = 0; k < 32; k++) {
        float ex = __expf(trans[j0 * TT + ibase + k]);
        float ey = __expf(trans[(j0 + 1) * TT + ibase + k]);
        e2[k] = pack2(ex, ey);
    }

    // ---- init partition p[t] = feats[b,0,t] + start[t]; compute running max ----
    float p = 0.f, fnext = 0.f;
    int mnext = 0;
    if (t < TT) {
        p = Fb[t] + start_t[t];
        fnext = Fb[TT + t];   // prefetch feat for s=1
        mnext = Mk[1];
        float m = p;
#pragma unroll
        for (int o = 16; o; o >>= 1) m = fmaxf(m, __shfl_xor_sync(0xffffffffu, m, o));
        if ((t & 31) == 0) sh_wmax[t >> 5] = m;
    }
    __syncthreads();
    float mmax = fmaxf(fmaxf(sh_wmax[0], sh_wmax[1]), fmaxf(sh_wmax[2], sh_wmax[3]));

    // ---- sequential scan over s = 1..S-1 ----
    for (int s = 1; s < SS; s++) {
        float fcur = 0.f;
        int mcur = 0;
        if (t < TT) {
            float qv = __expf(p - mmax);
            sh_q2[2 * t] = qv;
            sh_q2[2 * t + 1] = qv;
            fcur = fnext;
            mcur = mnext;
            if (s + 1 < SS) {
                fnext = Fb[(size_t)(s + 1) * TT + t];  // prefetch next step
                mnext = Mk[s + 1];
            }
        }
        __syncthreads();

        // matvec partial: this thread covers i in [ibase, ibase+32), j-pair (j0, j0+1)
        const unsigned long long* qd = ((const unsigned long long*)sh_q2) + ibase;
        unsigned long long acc0 = 0ull, acc1 = 0ull;
#pragma unroll
        for (int k = 0; k < 32; k += 2) {
            acc0 = ffma2(e2[k], qd[k], acc0);
            acc1 = ffma2(e2[k + 1], qd[k + 1], acc1);
        }
        float2 a0 = unpack2(acc0), a1 = unpack2(acc1);
        ((float2*)sh_part)[h * 64 + jp] = make_float2(a0.x + a1.x, a0.y + a1.y);
        __syncthreads();

        if (t < TT) {
            float ssum = sh_part[t] + sh_part[TT + t] + sh_part[2 * TT + t] + sh_part[3 * TT + t];
            float np = fcur + mmax + __logf(ssum);
            p = mcur ? np : p;
            float m = p;
#pragma unroll
            for (int o = 16; o; o >>= 1) m = fmaxf(m, __shfl_xor_sync(0xffffffffu, m, o));
            if ((t & 31) == 0) sh_wmax[t >> 5] = m;
        }
        __syncthreads();
        mmax = fmaxf(fmaxf(sh_wmax[0], sh_wmax[1]), fmaxf(sh_wmax[2], sh_wmax[3]));
    }

    // ---- fwd = LSE_j(p[j] + stop[j]) ----
    float v = -CUDART_INF_F;
    if (t < TT) {
        v = p + stop_t[t];
        float m = v;
#pragma unroll
        for (int o = 16; o; o >>= 1) m = fmaxf(m, __shfl_xor_sync(0xffffffffu, m, o));
        if ((t & 31) == 0) sh_wmax[t >> 5] = m;
    }
    __syncthreads();
    float M = fmaxf(fmaxf(sh_wmax[0], sh_wmax[1]), fmaxf(sh_wmax[2], sh_wmax[3]));
    if (t < TT) {
        float e = __expf(v - M);
#pragma unroll
        for (int o = 16; o; o >>= 1) e += __shfl_xor_sync(0xffffffffu, e, o);
        if ((t & 31) == 0) sh_redf[t >> 5] = e;
    }
    __syncthreads();
    float fwd = 0.f;
    if (t == 0) {
        float es = sh_redf[0] + sh_redf[1] + sh_redf[2] + sh_redf[3];
        fwd = M + __logf(es);
    }
    __syncthreads();

    // ---- gold score ----
    float facc = 0.f, lacc = 0.f;
    for (int s = t; s < SS; s += NT) {
        float mk = (float)Mk[s];
        int tg = Tg[s];
        facc += Fb[(size_t)s * TT + tg] * mk;
        lacc += mk;
        if (s >= 1) facc += trans[Tg[s - 1] * TT + tg] * mk;
    }
#pragma unroll
    for (int o = 16; o; o >>= 1) {
        facc += __shfl_xor_sync(0xffffffffu, facc, o);
        lacc += __shfl_xor_sync(0xffffffffu, lacc, o);
    }
    if ((t & 31) == 0) {
        sh_redf[t >> 5] = facc;
        sh_redl[t >> 5] = lacc;
    }
    __syncthreads();
    if (t == 0) {
        float fs = 0.f, ls = 0.f;
#pragma unroll
        for (int w = 0; w < NT / 32; w++) { fs += sh_redf[w]; ls += sh_redl[w]; }
        int len = (int)(ls + 0.5f);
        float gold = fs + start_t[Tg[0]] + stop_t[Tg[len - 1]];
        g_partial[b] = fwd - gold;
    }
}

__global__ void reduce64_kernel(float* __restrict__ out) {
    __shared__ float sw[2];
    int t = threadIdx.x;  // 64 threads
    float acc = g_partial[t];
#pragma unroll
    for (int o = 16; o; o >>= 1) acc += __shfl_xor_sync(0xffffffffu, acc, o);
    if ((t & 31) == 0) sw[t >> 5] = acc;
    __syncthreads();
    if (t == 0) out[0] = sw[0] + sw[1];
}

extern "C" void kernel_launch(void* const* d_in, const int* in_sizes, int n_in,
                              void* d_out, int out_size) {
    const float* feats = (const float*)d_in[0];
    const int* mask = (const int*)d_in[1];
    const int* tags = (const int*)d_in[2];
    const float* trans = (const float*)d_in[3];
    const float* start_t = (const float*)d_in[4];
    const float* stop_t = (const float*)d_in[5];
    float* out = (float*)d_out;

    crf_kernel<<<BB, NT>>>(feats, mask, tags, trans, start_t, stop_t);
    reduce64_kernel<<<1, 64>>>(out);
}

// round 2
// speedup vs baseline: 1.0599x; 1.0599x over previous
#include <cuda_runtime.h>
#include <math_constants.h>

#define BB 64
#define SS 512
#define TT 128
#define NT 256

__device__ float g_partial[BB];
__device__ unsigned int g_ctr = 0;

static __device__ __forceinline__ unsigned long long ffma2(unsigned long long a,
                                                           unsigned long long b,
                                                           unsigned long long c) {
    unsigned long long d;
    asm("fma.rn.f32x2 %0, %1, %2, %3;" : "=l"(d) : "l"(a), "l"(b), "l"(c));
    return d;
}
static __device__ __forceinline__ unsigned long long addf2(unsigned long long a,
                                                           unsigned long long b) {
    unsigned long long d;
    asm("add.rn.f32x2 %0, %1, %2;" : "=l"(d) : "l"(a), "l"(b));
    return d;
}
static __device__ __forceinline__ unsigned long long pack2(float x, float y) {
    unsigned long long d;
    asm("mov.b64 %0, {%1, %2};" : "=l"(d) : "f"(x), "f"(y));
    return d;
}
static __device__ __forceinline__ float2 unpack2(unsigned long long v) {
    float2 r;
    asm("mov.b64 {%0, %1}, %2;" : "=f"(r.x), "=f"(r.y) : "l"(v));
    return r;
}
static __device__ __forceinline__ float frcp(float x) {
    float r;
    asm("rcp.approx.f32 %0, %1;" : "=f"(r) : "f"(x));
    return r;
}

__global__ __launch_bounds__(NT, 1)
void crf_kernel(const float* __restrict__ feats,
                const int* __restrict__ mask,
                const int* __restrict__ tags,
                const float* __restrict__ trans,
                const float* __restrict__ start_t,
                const float* __restrict__ stop_t,
                float* __restrict__ out)
{
    __shared__ __align__(16) float sh_q[TT];        // linear-space partition
    __shared__ __align__(16) float sh_part[2 * TT]; // 2 i-half partials
    __shared__ float sh_q0[2];                      // double-buffered normalizer
    __shared__ float sh_wmax[4];
    __shared__ float sh_redf[NT / 32];
    __shared__ float sh_redl[NT / 32];
    __shared__ int sh_last;

    const int b = blockIdx.x;
    const int t = threadIdx.x;
    const float* Fb = feats + (size_t)b * SS * TT;
    const int* Mk = mask + b * SS;
    const int* Tg = tags + b * SS;

    const int j = t & (TT - 1);   // output tag column
    const int ihalf = t >> 7;     // which half of the i range
    const int i0 = ihalf * 64;

    // E[i][j] = exp(trans[j][i]); packed over i: e2[k] = (E[i0+2k][j], E[i0+2k+1][j])
    unsigned long long e2[32];
#pragma unroll
    for (int k = 0; k < 32; k++) {
        float2 tv = *(const float2*)(trans + j * TT + i0 + 2 * k);
        e2[k] = pack2(__expf(tv.x), __expf(tv.y));
    }

    // ---- init: q0[j] = exp(F[0,j] + start[j]);  C = 0 ----
    float q = 0.f, ef = 0.f, fnx = 0.f, fnx2 = 0.f, Csum = 0.f;
    int mc = 0, mnx = 0, mnx2 = 0;
    if (t < TT) {
        q = __expf(Fb[t] + start_t[t]);
        sh_q[t] = q;
        if (t == 0) sh_q0[0] = q;
        ef  = __expf(Fb[1 * TT + t]);   // exp(feat) for step 1, precomputed
        fnx  = Fb[2 * TT + t];
        fnx2 = Fb[3 * TT + t];
        mc = Mk[1]; mnx = Mk[2]; mnx2 = Mk[3];
    }
    __syncthreads();

    // ---- sequential scan: q'[j] = (sum_i q[i]*E[i][j]) * exp(f[j]) * rinv ----
    for (int s = 1; s < SS; s++) {
        float rinv = 0.f, sc = 0.f, efn = 0.f, fnew = 0.f;
        int mnew = 0;
        if (t < TT) {
            float q0p = sh_q0[(s - 1) & 1];   // lagged normalizer (written last iter)
            rinv = frcp(q0p);
            sc = ef * rinv;
            Csum -= __logf(rinv);             // exact accounting of applied scale
            efn = __expf(fnx);                // exp(feat) for step s+1
            if (s + 3 < SS) {
                fnew = Fb[(size_t)(s + 3) * TT + t];
                mnew = Mk[s + 3];
            }
        }

        // phase B: matvec partial. thread covers i in [i0, i0+64), column j.
        {
            const float4* q4 = (const float4*)(sh_q + i0);
            unsigned long long a0 = 0ull, a1 = 0ull, a2 = 0ull, a3 = 0ull;
#pragma unroll
            for (int k = 0; k < 16; k += 4) {
                float4 v0 = q4[k + 0], v1 = q4[k + 1], v2 = q4[k + 2], v3 = q4[k + 3];
                a0 = ffma2(e2[2 * k + 0], pack2(v0.x, v0.y), a0);
                a0 = ffma2(e2[2 * k + 1], pack2(v0.z, v0.w), a0);
                a1 = ffma2(e2[2 * k + 2], pack2(v1.x, v1.y), a1);
                a1 = ffma2(e2[2 * k + 3], pack2(v1.z, v1.w), a1);
                a2 = ffma2(e2[2 * k + 4], pack2(v2.x, v2.y), a2);
                a2 = ffma2(e2[2 * k + 5], pack2(v2.z, v2.w), a2);
                a3 = ffma2(e2[2 * k + 6], pack2(v3.x, v3.y), a3);
                a3 = ffma2(e2[2 * k + 7], pack2(v3.z, v3.w), a3);
            }
            unsigned long long sp = addf2(addf2(a0, a1), addf2(a2, a3));
            float2 aa = unpack2(sp);
            sh_part[ihalf * TT + j] = aa.x + aa.y;
        }
        __syncthreads();

        if (t < TT) {
            float ssum = sh_part[t] + sh_part[TT + t];
            float qn = ssum * sc;
            float qm = q * rinv;        // masked step: p unchanged => q scales by rinv
            q = mc ? qn : qm;
            sh_q[t] = q;
            if (t == 0) sh_q0[s & 1] = q;
            ef = efn; fnx = fnx2; fnx2 = fnew;
            mc = mnx; mnx = mnx2; mnx2 = mnew;
        }
        __syncthreads();
    }

    // ---- fwd = LSE_j(C + log q[j] + stop[j]) ----
    float v = -CUDART_INF_F;
    if (t < TT) {
        v = Csum + __logf(q) + stop_t[t];
        float m = v;
#pragma unroll
        for (int o = 16; o; o >>= 1) m = fmaxf(m, __shfl_xor_sync(0xffffffffu, m, o));
        if ((t & 31) == 0) sh_wmax[t >> 5] = m;
    }
    __syncthreads();
    float M = fmaxf(fmaxf(sh_wmax[0], sh_wmax[1]), fmaxf(sh_wmax[2], sh_wmax[3]));
    if (t < TT) {
        float e = __expf(v - M);
#pragma unroll
        for (int o = 16; o; o >>= 1) e += __shfl_xor_sync(0xffffffffu, e, o);
        if ((t & 31) == 0) sh_redf[t >> 5] = e;
    }
    __syncthreads();
    float fwd = 0.f;
    if (t == 0) {
        float es = sh_redf[0] + sh_redf[1] + sh_redf[2] + sh_redf[3];
        fwd = M + __logf(es);
    }
    __syncthreads();

    // ---- gold score ----
    float facc = 0.f, lacc = 0.f;
    for (int s = t; s < SS; s += NT) {
        float mk = (float)Mk[s];
        int tg = Tg[s];
        facc += Fb[(size_t)s * TT + tg] * mk;
        lacc += mk;
        if (s >= 1) facc += trans[Tg[s - 1] * TT + tg] * mk;
    }
#pragma unroll
    for (int o = 16; o; o >>= 1) {
        facc += __shfl_xor_sync(0xffffffffu, facc, o);
        lacc += __shfl_xor_sync(0xffffffffu, lacc, o);
    }
    if ((t & 31) == 0) {
        sh_redf[t >> 5] = facc;
        sh_redl[t >> 5] = lacc;
    }
    __syncthreads();
    if (t == 0) {
        float fs = 0.f, ls = 0.f;
#pragma unroll
        for (int w = 0; w < NT / 32; w++) { fs += sh_redf[w]; ls += sh_redl[w]; }
        int len = (int)(ls + 0.5f);
        float gold = fs + start_t[Tg[0]] + stop_t[Tg[len - 1]];
        g_partial[b] = fwd - gold;
    }

    // ---- fused deterministic final reduction: last block sums in index order ----
    if (t == 0) {
        __threadfence();
        unsigned int old = atomicInc(&g_ctr, BB - 1);   // wraps back to 0 each launch
        sh_last = (old == BB - 1) ? 1 : 0;
    }
    __syncthreads();
    if (sh_last) {
        if (t < BB) {
            float acc = __ldcg(&g_partial[t]);
#pragma unroll
            for (int o = 16; o; o >>= 1) acc += __shfl_xor_sync(0xffffffffu, acc, o);
            if ((t & 31) == 0) sh_redf[t >> 5] = acc;
        }
        __syncthreads();
        if (t == 0) out[0] = sh_redf[0] + sh_redf[1];
    }
}

extern "C" void kernel_launch(void* const* d_in, const int* in_sizes, int n_in,
                              void* d_out, int out_size) {
    const float* feats = (const float*)d_in[0];
    const int* mask = (const int*)d_in[1];
    const int* tags = (const int*)d_in[2];
    const float* trans = (const float*)d_in[3];
    const float* start_t = (const float*)d_in[4];
    const float* stop_t = (const float*)d_in[5];
    float* out = (float*)d_out;

    crf_kernel<<<BB, NT>>>(feats, mask, tags, trans, start_t, stop_t, out);
}

// round 3
// speedup vs baseline: 1.1244x; 1.0608x over previous
#include <cuda_runtime.h>
#include <math_constants.h>

#define BB 64
#define SS 512
#define TT 128
#define NT 256

__device__ float g_partial[BB];
__device__ unsigned int g_ctr = 0;

static __device__ __forceinline__ unsigned long long ffma2(unsigned long long a,
                                                           unsigned long long b,
                                                           unsigned long long c) {
    unsigned long long d;
    asm("fma.rn.f32x2 %0, %1, %2, %3;" : "=l"(d) : "l"(a), "l"(b), "l"(c));
    return d;
}
static __device__ __forceinline__ unsigned long long addf2(unsigned long long a,
                                                           unsigned long long b) {
    unsigned long long d;
    asm("add.rn.f32x2 %0, %1, %2;" : "=l"(d) : "l"(a), "l"(b));
    return d;
}
static __device__ __forceinline__ unsigned long long pack2(float x, float y) {
    unsigned long long d;
    asm("mov.b64 %0, {%1, %2};" : "=l"(d) : "f"(x), "f"(y));
    return d;
}
static __device__ __forceinline__ float2 unpack2(unsigned long long v) {
    float2 r;
    asm("mov.b64 {%0, %1}, %2;" : "=f"(r.x), "=f"(r.y) : "l"(v));
    return r;
}
static __device__ __forceinline__ float frcp(float x) {
    float r;
    asm("rcp.approx.f32 %0, %1;" : "=f"(r) : "f"(x));
    return r;
}

__global__ __launch_bounds__(NT, 1)
void crf_kernel(const float* __restrict__ feats,
                const int* __restrict__ mask,
                const int* __restrict__ tags,
                const float* __restrict__ trans,
                const float* __restrict__ start_t,
                const float* __restrict__ stop_t,
                float* __restrict__ out)
{
    __shared__ __align__(16) float sh_q[2][TT];   // double-buffered linear partition
    __shared__ int sh_mk[SS];                     // mask, preloaded once
    __shared__ float sh_v[TT];                    // final LSE staging
    __shared__ float sh_wmax[4];
    __shared__ float sh_redf[NT / 32];
    __shared__ float sh_redl[NT / 32];
    __shared__ int sh_last;

    const int b = blockIdx.x;
    const int t = threadIdx.x;
    const float* Fb = feats + (size_t)b * SS * TT;
    const int* Mk = mask + b * SS;
    const int* Tg = tags + b * SS;

    const int w = t >> 5;            // warp id: owns columns [16w, 16w+16)
    const int l = t & 31;
    const int j = w * 16 + (l >> 1); // this thread's output column
    const int half = l & 1;          // which i-half
    const int i0 = half * 64;

    // preload mask into shared
    for (int s = t; s < SS; s += NT) sh_mk[s] = Mk[s];

    // E[i][j] = exp(trans[j][i]); packed over i: e2[k] = (E[i0+2k][j], E[i0+2k+1][j])
    unsigned long long e2[32];
#pragma unroll
    for (int k = 0; k < 32; k++) {
        float2 tv = *(const float2*)(trans + j * TT + i0 + 2 * k);
        e2[k] = pack2(__expf(tv.x), __expf(tv.y));
    }

    // ---- init: q0[j] = exp(F[0,j] + start[j]);  C = 0 ----
    float qj = __expf(Fb[j] + start_t[j]);
    if (half == 0) sh_q[0][j] = qj;
    float Csum = 0.f;
    float ef   = __expf(Fb[1 * TT + j]);  // exp(feat) for step 1
    float fnx  = Fb[2 * TT + j];
    float fnx2 = Fb[3 * TT + j];
    __syncthreads();

    // ---- sequential scan, ONE barrier per step ----
#pragma unroll 2
    for (int s = 1; s < SS; s++) {
        const int p = (s - 1) & 1;

        // phase A (off critical path of the matvec consumers)
        float q0p = sh_q[p][0];
        float rinv = frcp(q0p);
        float sc = ef * rinv;
        Csum -= __logf(rinv);
        float efn = __expf(fnx);
        float fnew = 0.f;
        if (s + 3 < SS) fnew = Fb[(size_t)(s + 3) * TT + j];
        int mcur = sh_mk[s];

        // phase B: partial matvec, i in [i0, i0+64), column j
        const float4* q4 = (const float4*)(&sh_q[p][i0]);
        unsigned long long a0 = 0ull, a1 = 0ull, a2 = 0ull, a3 = 0ull;
#pragma unroll
        for (int k = 0; k < 16; k += 4) {
            float4 v0 = q4[k + 0], v1 = q4[k + 1], v2 = q4[k + 2], v3 = q4[k + 3];
            a0 = ffma2(e2[2 * k + 0], pack2(v0.x, v0.y), a0);
            a0 = ffma2(e2[2 * k + 1], pack2(v0.z, v0.w), a0);
            a1 = ffma2(e2[2 * k + 2], pack2(v1.x, v1.y), a1);
            a1 = ffma2(e2[2 * k + 3], pack2(v1.z, v1.w), a1);
            a2 = ffma2(e2[2 * k + 4], pack2(v2.x, v2.y), a2);
            a2 = ffma2(e2[2 * k + 5], pack2(v2.z, v2.w), a2);
            a3 = ffma2(e2[2 * k + 6], pack2(v3.x, v3.y), a3);
            a3 = ffma2(e2[2 * k + 7], pack2(v3.z, v3.w), a3);
        }
        unsigned long long sp = addf2(addf2(a0, a1), addf2(a2, a3));
        float2 aa = unpack2(sp);
        float part = aa.x + aa.y;

        // combine the two i-halves within the lane pair
        float ssum = part + __shfl_xor_sync(0xffffffffu, part, 1);

        // epilogue (both lanes compute; even lane stores)
        float qn = ssum * sc;
        float qm = qj * rinv;        // masked step: p unchanged => q scales by rinv
        qj = mcur ? qn : qm;
        if (half == 0) sh_q[s & 1][j] = qj;

        ef = efn; fnx = fnx2; fnx2 = fnew;
        __syncthreads();
    }

    // ---- fwd = LSE_j(C + log qj + stop[j]) ----
    if (half == 0) sh_v[j] = Csum + __logf(qj) + stop_t[j];
    __syncthreads();

    float v = -CUDART_INF_F;
    if (t < TT) {
        v = sh_v[t];
        float m = v;
#pragma unroll
        for (int o = 16; o; o >>= 1) m = fmaxf(m, __shfl_xor_sync(0xffffffffu, m, o));
        if ((t & 31) == 0) sh_wmax[t >> 5] = m;
    }
    __syncthreads();
    float M = fmaxf(fmaxf(sh_wmax[0], sh_wmax[1]), fmaxf(sh_wmax[2], sh_wmax[3]));
    if (t < TT) {
        float e = __expf(v - M);
#pragma unroll
        for (int o = 16; o; o >>= 1) e += __shfl_xor_sync(0xffffffffu, e, o);
        if ((t & 31) == 0) sh_redf[t >> 5] = e;
    }
    __syncthreads();
    float fwd = 0.f;
    if (t == 0) {
        float es = sh_redf[0] + sh_redf[1] + sh_redf[2] + sh_redf[3];
        fwd = M + __logf(es);
    }
    __syncthreads();

    // ---- gold score ----
    float facc = 0.f, lacc = 0.f;
    for (int s = t; s < SS; s += NT) {
        float mk = (float)sh_mk[s];
        int tg = Tg[s];
        facc += Fb[(size_t)s * TT + tg] * mk;
        lacc += mk;
        if (s >= 1) facc += trans[Tg[s - 1] * TT + tg] * mk;
    }
#pragma unroll
    for (int o = 16; o; o >>= 1) {
        facc += __shfl_xor_sync(0xffffffffu, facc, o);
        lacc += __shfl_xor_sync(0xffffffffu, lacc, o);
    }
    if ((t & 31) == 0) {
        sh_redf[t >> 5] = facc;
        sh_redl[t >> 5] = lacc;
    }
    __syncthreads();
    if (t == 0) {
        float fs = 0.f, ls = 0.f;
#pragma unroll
        for (int x = 0; x < NT / 32; x++) { fs += sh_redf[x]; ls += sh_redl[x]; }
        int len = (int)(ls + 0.5f);
        float gold = fs + start_t[Tg[0]] + stop_t[Tg[len - 1]];
        g_partial[b] = fwd - gold;
    }

    // ---- fused deterministic final reduction: last block sums in index order ----
    if (t == 0) {
        __threadfence();
        unsigned int old = atomicInc(&g_ctr, BB - 1);   // wraps back to 0 each launch
        sh_last = (old == BB - 1) ? 1 : 0;
    }
    __syncthreads();
    if (sh_last) {
        if (t < BB) {
            float acc = __ldcg(&g_partial[t]);
#pragma unroll
            for (int o = 16; o; o >>= 1) acc += __shfl_xor_sync(0xffffffffu, acc, o);
            if ((t & 31) == 0) sh_redf[t >> 5] = acc;
        }
        __syncthreads();
        if (t == 0) out[0] = sh_redf[0] + sh_redf[1];
    }
}

extern "C" void kernel_launch(void* const* d_in, const int* in_sizes, int n_in,
                              void* d_out, int out_size) {
    const float* feats = (const float*)d_in[0];
    const int* mask = (const int*)d_in[1];
    const int* tags = (const int*)d_in[2];
    const float* trans = (const float*)d_in[3];
    const float* start_t = (const float*)d_in[4];
    const float* stop_t = (const float*)d_in[5];
    float* out = (float*)d_out;

    crf_kernel<<<BB, NT>>>(feats, mask, tags, trans, start_t, stop_t, out);
}

// round 5
// speedup vs baseline: 1.2291x; 1.0931x over previous
#include <cuda_runtime.h>
#include <math_constants.h>

#define BB 64
#define SS 512
#define TT 128
#define NT 256

__device__ float g_partial[BB];
__device__ unsigned int g_ctr = 0;

static __device__ __forceinline__ unsigned long long ffma2(unsigned long long a,
                                                           unsigned long long b,
                                                           unsigned long long c) {
    unsigned long long d;
    asm("fma.rn.f32x2 %0, %1, %2, %3;" : "=l"(d) : "l"(a), "l"(b), "l"(c));
    return d;
}
static __device__ __forceinline__ unsigned long long addf2(unsigned long long a,
                                                           unsigned long long b) {
    unsigned long long d;
    asm("add.rn.f32x2 %0, %1, %2;" : "=l"(d) : "l"(a), "l"(b));
    return d;
}
static __device__ __forceinline__ unsigned long long pack2(float x, float y) {
    unsigned long long d;
    asm("mov.b64 %0, {%1, %2};" : "=l"(d) : "f"(x), "f"(y));
    return d;
}
static __device__ __forceinline__ float2 unpack2(unsigned long long v) {
    float2 r;
    asm("mov.b64 {%0, %1}, %2;" : "=f"(r.x), "=f"(r.y) : "l"(v));
    return r;
}

__global__ __launch_bounds__(NT, 1)
void crf_kernel(const float* __restrict__ feats,
                const int* __restrict__ mask,
                const int* __restrict__ tags,
                const float* __restrict__ trans,
                const float* __restrict__ start_t,
                const float* __restrict__ stop_t,
                float* __restrict__ out)
{
    __shared__ __align__(16) float sh_q[2][TT];   // double-buffered linear partition
    __shared__ int sh_mk[SS];                     // mask, preloaded once
    __shared__ float sh_v[TT];                    // final LSE staging
    __shared__ float sh_wmax[4];
    __shared__ float sh_redf[NT / 32];
    __shared__ float sh_redl[NT / 32];
    __shared__ int sh_last;

    const int b = blockIdx.x;
    const int t = threadIdx.x;
    const float* Fb = feats + (size_t)b * SS * TT;
    const int* Mk = mask + b * SS;
    const int* Tg = tags + b * SS;

    const int w = t >> 5;            // warp id: owns columns [16w, 16w+16)
    const int l = t & 31;
    const int j = w * 16 + (l >> 1); // this thread's output column
    const int half = l & 1;          // which i-half
    const int i0 = half * 64;

    // preload mask into shared
    for (int s = t; s < SS; s += NT) sh_mk[s] = Mk[s];

    // E[i][j] = exp(trans[j][i]); packed over i: e2[k] = (E[i0+2k][j], E[i0+2k+1][j])
    unsigned long long e2[32];
#pragma unroll
    for (int k = 0; k < 32; k++) {
        float2 tv = *(const float2*)(trans + j * TT + i0 + 2 * k);
        e2[k] = pack2(__expf(tv.x), __expf(tv.y));
    }

    // ---- init: q0[j] = exp(F[0,j] + start[j]) ----
    float qj = __expf(Fb[j] + start_t[j]);
    if (half == 0) sh_q[0][j] = qj;
    int Cexp = 0;                         // integer log2 offset accumulator
    float ef   = __expf(Fb[1 * TT + j]);  // exp(feat) for step 1
    float fnx  = Fb[2 * TT + j];
    float fnx2 = Fb[3 * TT + j];
    __syncthreads();

    // ---- sequential scan, ONE barrier per step ----
#pragma unroll 2
    for (int s = 1; s < SS; s++) {
        const int p = (s - 1) & 1;

        // phase A: exact power-of-2 normalizer from q[0]'s exponent (no MUFU)
        float q0p = sh_q[p][0];
        int e = (__float_as_int(q0p) >> 23) - 127;        // floor(log2 q0)
        float rinv = __int_as_float((127 - e) << 23);     // 2^{-e}, exact
        Cexp += e;
        float sc = ef * rinv;
        float efn = __expf(fnx);                          // exp(feat) for s+1
        int sp3 = (s + 3 < SS) ? (s + 3) : (SS - 1);
        float fnew = Fb[(size_t)sp3 * TT + j];
        int mcur = sh_mk[s];

        // phase B: partial matvec, i in [i0, i0+64), column j.
        // LDS.128 yields two b64 f32x2 operands directly — no pack MOVs.
        const ulonglong2* q8 = (const ulonglong2*)(&sh_q[p][i0]);
        unsigned long long a0 = 0ull, a1 = 0ull, a2 = 0ull, a3 = 0ull;
#pragma unroll
        for (int k = 0; k < 16; k += 4) {
            ulonglong2 v0 = q8[k + 0], v1 = q8[k + 1], v2 = q8[k + 2], v3 = q8[k + 3];
            a0 = ffma2(e2[2 * k + 0], v0.x, a0);
            a0 = ffma2(e2[2 * k + 1], v0.y, a0);
            a1 = ffma2(e2[2 * k + 2], v1.x, a1);
            a1 = ffma2(e2[2 * k + 3], v1.y, a1);
            a2 = ffma2(e2[2 * k + 4], v2.x, a2);
            a2 = ffma2(e2[2 * k + 5], v2.y, a2);
            a3 = ffma2(e2[2 * k + 6], v3.x, a3);
            a3 = ffma2(e2[2 * k + 7], v3.y, a3);
        }
        unsigned long long sp = addf2(addf2(a0, a1), addf2(a2, a3));
        float2 aa = unpack2(sp);
        float part = aa.x + aa.y;

        // combine the two i-halves within the lane pair
        float ssum = part + __shfl_xor_sync(0xffffffffu, part, 1);

        // epilogue
        float qn = ssum * sc;
        float qm = qj * rinv;        // masked step: exact pow2 rescale
        qj = mcur ? qn : qm;
        if (half == 0) sh_q[s & 1][j] = qj;

        ef = efn; fnx = fnx2; fnx2 = fnew;
        __syncthreads();
    }

    // ---- fwd = LSE_j(Cexp*ln2 + log qj + stop[j]) ----
    if (half == 0) sh_v[j] = (float)Cexp * 0.69314718055994531f + __logf(qj) + stop_t[j];
    __syncthreads();

    float v = -CUDART_INF_F;
    if (t < TT) {
        v = sh_v[t];
        float m = v;
#pragma unroll
        for (int o = 16; o; o >>= 1) m = fmaxf(m, __shfl_xor_sync(0xffffffffu, m, o));
        if ((t & 31) == 0) sh_wmax[t >> 5] = m;
    }
    __syncthreads();
    float M = fmaxf(fmaxf(sh_wmax[0], sh_wmax[1]), fmaxf(sh_wmax[2], sh_wmax[3]));
    if (t < TT) {
        float e = __expf(v - M);
#pragma unroll
        for (int o = 16; o; o >>= 1) e += __shfl_xor_sync(0xffffffffu, e, o);
        if ((t & 31) == 0) sh_redf[t >> 5] = e;
    }
    __syncthreads();
    float fwd = 0.f;
    if (t == 0) {
        float es = sh_redf[0] + sh_redf[1] + sh_redf[2] + sh_redf[3];
        fwd = M + __logf(es);
    }
    __syncthreads();

    // ---- gold score ----
    float facc = 0.f, lacc = 0.f;
    for (int s = t; s < SS; s += NT) {
        float mk = (float)sh_mk[s];
        int tg = Tg[s];
        facc += Fb[(size_t)s * TT + tg] * mk;
        lacc += mk;
        if (s >= 1) facc += trans[Tg[s - 1] * TT + tg] * mk;
    }
#pragma unroll
    for (int o = 16; o; o >>= 1) {
        facc += __shfl_xor_sync(0xffffffffu, facc, o);
        lacc += __shfl_xor_sync(0xffffffffu, lacc, o);
    }
    if ((t & 31) == 0) {
        sh_redf[t >> 5] = facc;
        sh_redl[t >> 5] = lacc;
    }
    __syncthreads();
    if (t == 0) {
        float fs = 0.f, ls = 0.f;
#pragma unroll
        for (int x = 0; x < NT / 32; x++) { fs += sh_redf[x]; ls += sh_redl[x]; }
        int len = (int)(ls + 0.5f);
        float gold = fs + start_t[Tg[0]] + stop_t[Tg[len - 1]];
        g_partial[b] = fwd - gold;
    }

    // ---- fused deterministic final reduction ----
    if (t == 0) {
        __threadfence();
        unsigned int old = atomicInc(&g_ctr, BB - 1);   // wraps back to 0 each launch
        sh_last = (old == BB - 1) ? 1 : 0;
    }
    __syncthreads();
    if (sh_last) {
        if (t < BB) {
            float acc = __ldcg(&g_partial[t]);
#pragma unroll
            for (int o = 16; o; o >>= 1) acc += __shfl_xor_sync(0xffffffffu, acc, o);
            if ((t & 31) == 0) sh_redf[t >> 5] = acc;
        }
        __syncthreads();
        if (t == 0) out[0] = sh_redf[0] + sh_redf[1];
    }
}

extern "C" void kernel_launch(void* const* d_in, const int* in_sizes, int n_in,
                              void* d_out, int out_size) {
    const float* feats = (const float*)d_in[0];
    const int* mask = (const int*)d_in[1];
    const int* tags = (const int*)d_in[2];
    const float* trans = (const float*)d_in[3];
    const float* start_t = (const float*)d_in[4];
    const float* stop_t = (const float*)d_in[5];
    float* out = (float*)d_out;

    crf_kernel<<<BB, NT>>>(feats, mask, tags, trans, start_t, stop_t, out);
}